// round 9
// baseline (speedup 1.0000x reference)
#include <cuda_runtime.h>
#include <math.h>

#define NB     64
#define TT     1024
#define ML     256
#define PP     (TT - 1)
#define NTHR   128          // 4 warps per CTA
#define CPB    16           // CTAs per batch
#define NBLK   (NB * CPB)   // 1024 CTAs, single wave
#define GL     8            // lags per group; 32 groups x 2 position-halves

// Per-CTA partial fit stats: [Sm, S1, S2] in double.
__device__ double g_part[NBLK][3];
__device__ unsigned int g_count;   // zero-init; last block resets each launch

// lengths may arrive as int64 or int32 (JAX x64 flag dependent).
__device__ __forceinline__ int get_len(const void* Lp, int b) {
    const long long* L64 = (const long long*)Lp;
    long long v0 = L64[0];
    if (v0 >= 1 && v0 <= (long long)TT) return (int)L64[b];
    return ((const int*)Lp)[b];
}

// ---------------------------------------------------------------------------
// Sum-of-squares expansion:
//   sum_{p<n} |x_{p+l}-x_p|^2 = (E[len]-E[l]) + E[n] - 2*C(l,n),
//   C(l,n) = sum_{p<n} x_{p+l}.x_p,  E = exclusive prefix sum of |x_i|^2.
// Inner loop is pure cross-correlation: 2 FFMA per pair.
// 1024 CTAs (16/batch), 128 threads; CTA owns 2 adjacent 8-lag groups, each
// group split across a pair of warps by position blocks. SMEM trajectory +
// 1-shifted copy (aligned float4 endpoint loads) + double prefix-sum table.
// Last-block deterministic final reduction.
// ---------------------------------------------------------------------------
__global__ void __launch_bounds__(NTHR)
fused_kernel(const float* __restrict__ traj,
             const void*  __restrict__ lengths,
             const float* __restrict__ alpha_pred,
             float* __restrict__ out)
{
    __shared__ float4 sh4[TT / 2];     // positions 2k,2k+1 per float4
    __shared__ float4 sh14[TT / 2];    // shifted copy: sh1[i] = traj[i+1]
    __shared__ double sE[TT + 1];      // exclusive prefix of |x|^2
    __shared__ double swsum[4];        // per-warp scan totals
    __shared__ float  sacc[2][2][GL];  // [group-in-CTA][half][lag]
    __shared__ float  spt[NB];
    __shared__ unsigned int s_last;

    const int blk  = blockIdx.x;
    const int b    = blk >> 4;        // batch
    const int part = blk & 15;        // lag slice (2 groups per CTA)

    if (threadIdx.x == 0) s_last = 0u;

    float2* shw  = (float2*)sh4;
    float2* sh1w = (float2*)sh14;
    const float2* sh   = (const float2*)sh4;
    const float4* sh1q = (const float4*)sh14;

    const int warp = threadIdx.x >> 5;
    const int lane = threadIdx.x & 31;

    const float2* row = (const float2*)(traj + (size_t)b * TT * 2);
    #pragma unroll
    for (int i = threadIdx.x; i < TT; i += NTHR) shw[i] = row[i];
    __syncthreads();
    #pragma unroll
    for (int i = threadIdx.x; i < TT; i += NTHR)
        sh1w[i] = (i < TT - 1) ? sh[i + 1] : make_float2(0.f, 0.f);

    // ---- block scan of |x_i|^2 (8 consecutive elems per thread) ----
    {
        const int i0 = threadIdx.x * 8;
        double loc[8];
        double s = 0.0;
        #pragma unroll
        for (int j = 0; j < 8; j++) {
            float2 a = sh[i0 + j];
            s += (double)(a.x * a.x + a.y * a.y);
            loc[j] = s;                            // inclusive within thread
        }
        // warp-exclusive scan of thread totals
        double excl = 0.0;
        double v = s;
        #pragma unroll
        for (int o = 1; o < 32; o <<= 1) {
            double u = __shfl_up_sync(0xffffffffu, v, o);
            if (lane >= o) v += u;
        }
        excl = v - s;                               // exclusive of this thread
        if (lane == 31) swsum[warp] = v;            // warp total
        __syncthreads();
        double woff = 0.0;
        #pragma unroll
        for (int w = 0; w < 4; w++) woff += (w < warp) ? swsum[w] : 0.0;
        const double base = woff + excl;
        #pragma unroll
        for (int j = 0; j < 8; j++) sE[i0 + j + 1] = base + loc[j];
        if (threadIdx.x == 0) sE[0] = 0.0;
    }
    __syncthreads();

    const int   len   = get_len(lengths, b);
    const float alpha = alpha_pred[b];

    const int grp  = warp >> 1;                  // 0 or 1 within CTA
    const int half = warp & 1;                   // position half
    const int g    = part * 2 + grp;             // global group id [0,32)
    const int l0   = 1 + GL * g;                 // first lag (odd)

    int nmin = len - (l0 + GL - 1);
    if (nmin < 0) nmin = 0; if (nmin > PP) nmin = PP;
    int nmax = len - l0;
    if (nmax < 0) nmax = 0; if (nmax > PP) nmax = PP;

    float acc[GL];                               // cross-correlation C_j
    #pragma unroll
    for (int j = 0; j < GL; j++) acc[j] = 0.f;

    // --- main region: 64-position blocks interleaved between the 2 halves ---
    const int imax = nmin >> 6;
    for (int i = half; i < imax; i += 2) {
        const int p  = (i << 6) + (lane << 1);   // even
        float4 aq = sh4[p >> 1];                 // positions p, p+1
        const int k0 = (p + l0 - 1) >> 1;        // l0 odd -> aligned
        float4 e0q = sh1q[k0];
        float4 e1q = sh1q[k0 + 1];
        float4 e2q = sh1q[k0 + 2];
        float4 e3q = sh1q[k0 + 3];
        float2 e8  = sh[p + l0 + 8];

        float ex[9], ey[9];
        ex[0]=e0q.x; ey[0]=e0q.y;  ex[1]=e0q.z; ey[1]=e0q.w;
        ex[2]=e1q.x; ey[2]=e1q.y;  ex[3]=e1q.z; ey[3]=e1q.w;
        ex[4]=e2q.x; ey[4]=e2q.y;  ex[5]=e2q.z; ey[5]=e2q.w;
        ex[6]=e3q.x; ey[6]=e3q.y;  ex[7]=e3q.z; ey[7]=e3q.w;
        ex[8]=e8.x;  ey[8]=e8.y;

        #pragma unroll
        for (int j = 0; j < GL; j++) {
            acc[j] += ex[j]   * aq.x + ey[j]   * aq.y
                    + ex[j+1] * aq.z + ey[j+1] * aq.w;   // 4 FFMA
        }
    }

    // --- masked tail (half 1 only) ---
    if (half == 1) {
        for (int p = (imax << 6) + lane; p < nmax; p += 32) {
            float2 a = sh[p];
            #pragma unroll
            for (int j = 0; j < GL; j++) {
                int nj = len - (l0 + j);
                if (nj > PP) nj = PP;
                if (p < nj) {
                    float2 e = sh[p + l0 + j];
                    acc[j] += e.x * a.x + e.y * a.y;
                }
            }
        }
    }

    // --- warp reduce, stash per-half sums in SMEM ---
    #pragma unroll
    for (int j = 0; j < GL; j++) {
        #pragma unroll
        for (int o = 16; o > 0; o >>= 1)
            acc[j] += __shfl_xor_sync(0xffffffffu, acc[j], o);
    }
    if (lane == 0) {
        #pragma unroll
        for (int j = 0; j < GL; j++) sacc[grp][half][j] = acc[j];
    }
    __syncthreads();

    // --- epilogue: warp 0 lanes 0..15 each finish one lag ---
    if (warp == 0) {
        double sm = 0.0, s1 = 0.0, s2 = 0.0;
        if (lane < 16) {
            const int lg   = lane >> 3;
            const int jj   = lane & 7;
            const int lag  = 1 + GL * (part * 2 + lg) + jj;
            int nj = len - lag;
            if (nj < 0) nj = 0;
            const double C = (double)(sacc[lg][0][jj] + sacc[lg][1][jj]);
            double msd = 0.0;
            if (nj > 0) {
                const double ss = (sE[len] - sE[lag]) + sE[nj] - 2.0 * C;
                msd = ss / (double)nj;
                if (msd < 0.0) msd = 0.0;          // guard rounding before log
            }
            const float r = logf((float)msd + 1e-8f) - alpha * logf((float)lag);
            if (len > lag) {
                sm = 1.0; s1 = (double)r; s2 = (double)r * (double)r;
            }
        }
        #pragma unroll
        for (int o = 16; o > 0; o >>= 1) {
            sm += __shfl_xor_sync(0xffffffffu, sm, o);
            s1 += __shfl_xor_sync(0xffffffffu, s1, o);
            s2 += __shfl_xor_sync(0xffffffffu, s2, o);
        }
        if (lane == 0) {
            g_part[blk][0] = sm; g_part[blk][1] = s1; g_part[blk][2] = s2;
        }
    }
    __syncthreads();

    if (threadIdx.x == 0) {
        __threadfence();
        unsigned int old = atomicAdd(&g_count, 1u);
        s_last = (old == NBLK - 1) ? 1u : 0u;
    }
    __syncthreads();

    if (s_last) {
        __threadfence();
        const int t = threadIdx.x;
        if (t < NB) {
            double Sm = 0, S1 = 0, S2 = 0;
            #pragma unroll
            for (int i = 0; i < CPB; i++) {
                Sm += g_part[CPB * t + i][0];
                S1 += g_part[CPB * t + i][1];
                S2 += g_part[CPB * t + i][2];
            }
            double denom = (Sm > 1.0) ? Sm : 1.0;
            double I = S1 / denom;
            double pt = (S2 - 2.0 * I * S1 + I * I * Sm) / denom;
            spt[t] = (float)pt;
        }
        __syncthreads();
        if (threadIdx.x < 32) {
            float v = spt[threadIdx.x] + spt[threadIdx.x + 32];
            #pragma unroll
            for (int o = 16; o > 0; o >>= 1)
                v += __shfl_xor_sync(0xffffffffu, v, o);
            if (threadIdx.x == 0) {
                g_count = 0;                 // reset for next graph replay
                __threadfence();
                out[0] = v / (float)NB;
            }
        }
    }
}

// ---------------------------------------------------------------------------
// Inputs: [0] alpha_pred f32[64], [1] trajectory f32[64,1024,2],
// [2] lengths int64/int32[64]. Output: 1 float.
// ---------------------------------------------------------------------------
extern "C" void kernel_launch(void* const* d_in, const int* in_sizes, int n_in,
                              void* d_out, int out_size)
{
    const float* alpha = (const float*)d_in[0];
    const float* traj  = (const float*)d_in[1];
    const void*  lens  = d_in[2];
    float* out = (float*)d_out;

    fused_kernel<<<NBLK, NTHR>>>(traj, lens, alpha, out);
}

// round 11
// speedup vs baseline: 1.1667x; 1.1667x over previous
#include <cuda_runtime.h>
#include <math.h>

#define NB     64
#define TT     1024
#define ML     256
#define PP     (TT - 1)
#define NTHR   128          // 4 warps per CTA = 4 position-quarters
#define GPB    32           // groups (CTAs) per batch
#define NBLK   (NB * GPB)   // 2048 CTAs
#define GL     8            // lags per group

// Per-CTA partial fit stats: [Sm, S1, S2] in double.
__device__ double g_part[NBLK][3];
__device__ unsigned int g_count;   // zero-init; last block resets each launch

// lengths may arrive as int64 or int32 (JAX x64 flag dependent).
__device__ __forceinline__ int get_len(const void* Lp, int b) {
    const long long* L64 = (const long long*)Lp;
    long long v0 = L64[0];
    if (v0 >= 1 && v0 <= (long long)TT) return (int)L64[b];
    return ((const int*)Lp)[b];
}

// ---------------------------------------------------------------------------
// 2048 CTAs (32/batch), 128 threads. Each CTA owns ONE group of 8 consecutive
// lags [l0, l0+7], l0 = 8g+1 (odd); its 4 warps split positions in interleaved
// 64-position blocks (tail on warp 3). Endpoints for all 8 lags of a position
// pair come from ONE aligned 10-position window (5 x LDS.128) since the window
// start p+l0-1 is even -> no shifted SMEM copy needed. Direct displacement
// math (no prefix-sum algebra). Warp halves combine via SMEM; per-lag fit
// stats in double; last-block deterministic reduction.
// ---------------------------------------------------------------------------
__global__ void __launch_bounds__(NTHR, 14)
fused_kernel(const float* __restrict__ traj,
             const void*  __restrict__ lengths,
             const float* __restrict__ alpha_pred,
             float* __restrict__ out)
{
    __shared__ float4 sh4[TT / 2];    // positions 2k,2k+1 per float4
    __shared__ float  sacc[4][GL];    // per-warp partial sums
    __shared__ float  spt[NB];
    __shared__ unsigned int s_last;

    const int blk = blockIdx.x;
    const int b   = blk >> 5;         // batch
    const int g   = blk & 31;         // group id [0,32)
    const int l0  = 1 + GL * g;       // first lag (odd)

    if (threadIdx.x == 0) s_last = 0u;

    const float2* sh = (const float2*)sh4;

    // prologue: 512 float4s, 4 iterations
    const float4* rowq = (const float4*)(traj + (size_t)b * TT * 2);
    #pragma unroll
    for (int i = threadIdx.x; i < TT / 2; i += NTHR) sh4[i] = rowq[i];
    __syncthreads();

    const int len  = get_len(lengths, b);
    const int warp = threadIdx.x >> 5;
    const int lane = threadIdx.x & 31;

    int nmin = len - (l0 + GL - 1);
    if (nmin < 0) nmin = 0; if (nmin > PP) nmin = PP;
    int nmax = len - l0;
    if (nmax < 0) nmax = 0; if (nmax > PP) nmax = PP;

    float acc[GL];
    #pragma unroll
    for (int j = 0; j < GL; j++) acc[j] = 0.f;

    // --- main region: 64-position blocks, interleaved across 4 warps ---
    const int imax = nmin >> 6;
    for (int i = warp; i < imax; i += 4) {
        const int p  = (i << 6) + (lane << 1);   // even
        float4 aq = sh4[p >> 1];                 // positions p, p+1
        const int k0 = (p + l0 - 1) >> 1;        // window start (even pos)
        float4 q0 = sh4[k0];                     // pos p+l0-1 .. p+l0
        float4 q1 = sh4[k0 + 1];
        float4 q2 = sh4[k0 + 2];
        float4 q3 = sh4[k0 + 3];
        float4 q4 = sh4[k0 + 4];                 // .. p+l0+8

        float vx[10], vy[10];                    // v[t] = pos p+l0-1+t
        vx[0]=q0.x; vy[0]=q0.y;  vx[1]=q0.z; vy[1]=q0.w;
        vx[2]=q1.x; vy[2]=q1.y;  vx[3]=q1.z; vy[3]=q1.w;
        vx[4]=q2.x; vy[4]=q2.y;  vx[5]=q2.z; vy[5]=q2.w;
        vx[6]=q3.x; vy[6]=q3.y;  vx[7]=q3.z; vy[7]=q3.w;
        vx[8]=q4.x; vy[8]=q4.y;  vx[9]=q4.z; vy[9]=q4.w;

        #pragma unroll
        for (int j = 0; j < GL; j++) {
            // pair (p, p+l0+j) and (p+1, p+1+l0+j)
            float dx0 = vx[j+1] - aq.x, dy0 = vy[j+1] - aq.y;
            float dx1 = vx[j+2] - aq.z, dy1 = vy[j+2] - aq.w;
            acc[j] += dx0 * dx0 + dy0 * dy0;
            acc[j] += dx1 * dx1 + dy1 * dy1;
        }
    }

    // --- masked tail (warp 3 only): positions beyond the last full block ---
    if (warp == 3) {
        for (int p = (imax << 6) + lane; p < nmax; p += 32) {
            float2 a = sh[p];
            #pragma unroll
            for (int j = 0; j < GL; j++) {
                int nj = len - (l0 + j);
                if (nj > PP) nj = PP;
                if (p < nj) {
                    float2 e = sh[p + l0 + j];
                    float dx = e.x - a.x, dy = e.y - a.y;
                    acc[j] += dx * dx + dy * dy;
                }
            }
        }
    }

    // --- warp reduce, stash per-warp sums in SMEM ---
    #pragma unroll
    for (int j = 0; j < GL; j++) {
        #pragma unroll
        for (int o = 16; o > 0; o >>= 1)
            acc[j] += __shfl_xor_sync(0xffffffffu, acc[j], o);
    }
    if (lane == 0) {
        #pragma unroll
        for (int j = 0; j < GL; j++) sacc[warp][j] = acc[j];
    }
    __syncthreads();

    // --- epilogue: warp 0 lanes 0..7 each finish one lag ---
    if (warp == 0) {
        double sm = 0.0, s1 = 0.0, s2 = 0.0;
        if (lane < GL) {
            const int lag = l0 + lane;
            int nj = len - lag;
            if (nj < 0) nj = 0; if (nj > PP) nj = PP;
            const float tot = sacc[0][lane] + sacc[1][lane]
                            + sacc[2][lane] + sacc[3][lane];
            const float msd = (nj > 0) ? tot / (float)nj : 0.f;
            const float alpha = alpha_pred[b];
            const float r = logf(msd + 1e-8f) - alpha * logf((float)lag);
            if (len > lag) {
                sm = 1.0; s1 = (double)r; s2 = (double)r * (double)r;
            }
        }
        #pragma unroll
        for (int o = 16; o > 0; o >>= 1) {
            sm += __shfl_xor_sync(0xffffffffu, sm, o);
            s1 += __shfl_xor_sync(0xffffffffu, s1, o);
            s2 += __shfl_xor_sync(0xffffffffu, s2, o);
        }
        if (lane == 0) {
            g_part[blk][0] = sm; g_part[blk][1] = s1; g_part[blk][2] = s2;
        }
    }
    __syncthreads();

    if (threadIdx.x == 0) {
        __threadfence();
        unsigned int old = atomicAdd(&g_count, 1u);
        s_last = (old == NBLK - 1) ? 1u : 0u;
    }
    __syncthreads();

    if (s_last) {
        __threadfence();
        const int t = threadIdx.x;
        if (t < NB) {
            double Sm = 0, S1 = 0, S2 = 0;
            #pragma unroll 8
            for (int i = 0; i < GPB; i++) {
                Sm += g_part[GPB * t + i][0];
                S1 += g_part[GPB * t + i][1];
                S2 += g_part[GPB * t + i][2];
            }
            double denom = (Sm > 1.0) ? Sm : 1.0;
            double I = S1 / denom;
            double pt = (S2 - 2.0 * I * S1 + I * I * Sm) / denom;
            spt[t] = (float)pt;
        }
        __syncthreads();
        if (threadIdx.x < 32) {
            float v = spt[threadIdx.x] + spt[threadIdx.x + 32];
            #pragma unroll
            for (int o = 16; o > 0; o >>= 1)
                v += __shfl_xor_sync(0xffffffffu, v, o);
            if (threadIdx.x == 0) {
                g_count = 0;                 // reset for next graph replay
                __threadfence();
                out[0] = v / (float)NB;
            }
        }
    }
}

// ---------------------------------------------------------------------------
// Inputs: [0] alpha_pred f32[64], [1] trajectory f32[64,1024,2],
// [2] lengths int64/int32[64]. Output: 1 float.
// ---------------------------------------------------------------------------
extern "C" void kernel_launch(void* const* d_in, const int* in_sizes, int n_in,
                              void* d_out, int out_size)
{
    const float* alpha = (const float*)d_in[0];
    const float* traj  = (const float*)d_in[1];
    const void*  lens  = d_in[2];
    float* out = (float*)d_out;

    fused_kernel<<<NBLK, NTHR>>>(traj, lens, alpha, out);
}

// round 13
// speedup vs baseline: 1.4393x; 1.2336x over previous
#include <cuda_runtime.h>
#include <math.h>

#define NB     64
#define TT     1024
#define ML     256
#define PP     (TT - 1)
#define NTHR   128          // 4 warps: 2 lag-groups x 2 position-halves
#define CPB    16           // CTAs per batch
#define NBLK   (NB * CPB)   // 1024 CTAs (~7/SM, single wave)
#define GL     8            // lags per group

// Per-CTA partial fit stats: [Sm, S1, S2] in double.
__device__ double g_part[NBLK][3];
__device__ unsigned int g_count;   // zero-init; last block resets each launch

// lengths may arrive as int64 or int32 (JAX x64 flag dependent).
__device__ __forceinline__ int get_len(const void* Lp, int b) {
    const long long* L64 = (const long long*)Lp;
    long long v0 = L64[0];
    if (v0 >= 1 && v0 <= (long long)TT) return (int)L64[b];
    return ((const int*)Lp)[b];
}

// ---------------------------------------------------------------------------
// 1024 CTAs (16/batch), 128 threads. CTA owns 2 adjacent 8-lag groups; each
// group is split across a warp pair by interleaved 64-position blocks (tail on
// half 1). Endpoints for all 8 lags of a position pair come from ONE aligned
// 10-position window (5 x LDS.128; window start p+l0-1 is even since l0 odd).
// Main loop unrolled x2 with all 12 LDS hoisted ahead of the FP block so each
// warp holds ~12 independent LDS in flight (attacks the load-use serialization
// seen at regs=32). Registers deliberately relaxed: __launch_bounds__(128, 7).
// ---------------------------------------------------------------------------
__global__ void __launch_bounds__(NTHR, 7)
fused_kernel(const float* __restrict__ traj,
             const void*  __restrict__ lengths,
             const float* __restrict__ alpha_pred,
             float* __restrict__ out)
{
    __shared__ float4 sh4[TT / 2];     // positions 2k,2k+1 per float4
    __shared__ float  sacc[2][2][GL];  // [group-in-CTA][half][lag]
    __shared__ float  spt[NB];
    __shared__ unsigned int s_last;

    const int blk  = blockIdx.x;
    const int b    = blk >> 4;        // batch
    const int part = blk & 15;        // lag slice (2 groups per CTA)

    if (threadIdx.x == 0) s_last = 0u;

    const float2* sh = (const float2*)sh4;

    const float4* rowq = (const float4*)(traj + (size_t)b * TT * 2);
    #pragma unroll
    for (int i = threadIdx.x; i < TT / 2; i += NTHR) sh4[i] = rowq[i];
    __syncthreads();

    const int len  = get_len(lengths, b);
    const int warp = threadIdx.x >> 5;
    const int lane = threadIdx.x & 31;

    const int grp  = warp >> 1;                  // 0 or 1 within CTA
    const int half = warp & 1;                   // position half
    const int g    = part * 2 + grp;             // global group id [0,32)
    const int l0   = 1 + GL * g;                 // first lag (odd)

    int nmin = len - (l0 + GL - 1);
    if (nmin < 0) nmin = 0;
    if (nmin > PP) nmin = PP;
    int nmax = len - l0;
    if (nmax < 0) nmax = 0;
    if (nmax > PP) nmax = PP;

    float acc[GL];
    #pragma unroll
    for (int j = 0; j < GL; j++) acc[j] = 0.f;

    const int imax = nmin >> 6;
    int i = half;

    // --- main region, unrolled x2: blocks i and i+2 (this half's stride is 2) ---
    for (; i + 2 < imax; i += 4) {
        const int pA = (i << 6) + (lane << 1);
        const int pB = pA + 128;
        const int kA = (pA + l0 - 1) >> 1;       // even window start
        const int kB = kA + 64;

        // hoist all 12 LDS.128 (independent)
        float4 aqA = sh4[pA >> 1];
        float4 a0 = sh4[kA],     a1 = sh4[kA + 1], a2 = sh4[kA + 2];
        float4 a3 = sh4[kA + 3], a4 = sh4[kA + 4];
        float4 aqB = sh4[pB >> 1];
        float4 b0 = sh4[kB],     b1 = sh4[kB + 1], b2 = sh4[kB + 2];
        float4 b3 = sh4[kB + 3], b4 = sh4[kB + 4];

        float ax[10], ay[10], bx[10], by[10];    // window pos l0-1 .. l0+8
        ax[0]=a0.x; ay[0]=a0.y; ax[1]=a0.z; ay[1]=a0.w;
        ax[2]=a1.x; ay[2]=a1.y; ax[3]=a1.z; ay[3]=a1.w;
        ax[4]=a2.x; ay[4]=a2.y; ax[5]=a2.z; ay[5]=a2.w;
        ax[6]=a3.x; ay[6]=a3.y; ax[7]=a3.z; ay[7]=a3.w;
        ax[8]=a4.x; ay[8]=a4.y; ax[9]=a4.z; ay[9]=a4.w;
        bx[0]=b0.x; by[0]=b0.y; bx[1]=b0.z; by[1]=b0.w;
        bx[2]=b1.x; by[2]=b1.y; bx[3]=b1.z; by[3]=b1.w;
        bx[4]=b2.x; by[4]=b2.y; bx[5]=b2.z; by[5]=b2.w;
        bx[6]=b3.x; by[6]=b3.y; bx[7]=b3.z; by[7]=b3.w;
        bx[8]=b4.x; by[8]=b4.y; bx[9]=b4.z; by[9]=b4.w;

        #pragma unroll
        for (int j = 0; j < GL; j++) {
            float dx0 = ax[j+1] - aqA.x, dy0 = ay[j+1] - aqA.y;
            float dx1 = ax[j+2] - aqA.z, dy1 = ay[j+2] - aqA.w;
            float ex0 = bx[j+1] - aqB.x, ey0 = by[j+1] - aqB.y;
            float ex1 = bx[j+2] - aqB.z, ey1 = by[j+2] - aqB.w;
            acc[j] += dx0 * dx0 + dy0 * dy0;
            acc[j] += dx1 * dx1 + dy1 * dy1;
            acc[j] += ex0 * ex0 + ey0 * ey0;
            acc[j] += ex1 * ex1 + ey1 * ey1;
        }
    }

    // --- leftover single block for this half ---
    if (i < imax) {
        const int p  = (i << 6) + (lane << 1);
        const int k0 = (p + l0 - 1) >> 1;
        float4 aq = sh4[p >> 1];
        float4 q0 = sh4[k0],     q1 = sh4[k0 + 1], q2 = sh4[k0 + 2];
        float4 q3 = sh4[k0 + 3], q4 = sh4[k0 + 4];

        float vx[10], vy[10];
        vx[0]=q0.x; vy[0]=q0.y; vx[1]=q0.z; vy[1]=q0.w;
        vx[2]=q1.x; vy[2]=q1.y; vx[3]=q1.z; vy[3]=q1.w;
        vx[4]=q2.x; vy[4]=q2.y; vx[5]=q2.z; vy[5]=q2.w;
        vx[6]=q3.x; vy[6]=q3.y; vx[7]=q3.z; vy[7]=q3.w;
        vx[8]=q4.x; vy[8]=q4.y; vx[9]=q4.z; vy[9]=q4.w;

        #pragma unroll
        for (int j = 0; j < GL; j++) {
            float dx0 = vx[j+1] - aq.x, dy0 = vy[j+1] - aq.y;
            float dx1 = vx[j+2] - aq.z, dy1 = vy[j+2] - aq.w;
            acc[j] += dx0 * dx0 + dy0 * dy0;
            acc[j] += dx1 * dx1 + dy1 * dy1;
        }
    }

    // --- masked tail (half 1 only): positions beyond the last full block ---
    if (half == 1) {
        for (int p = (imax << 6) + lane; p < nmax; p += 32) {
            float2 a = sh[p];
            #pragma unroll
            for (int j = 0; j < GL; j++) {
                int nj = len - (l0 + j);
                if (nj > PP) nj = PP;
                if (p < nj) {
                    float2 e = sh[p + l0 + j];
                    float dx = e.x - a.x, dy = e.y - a.y;
                    acc[j] += dx * dx + dy * dy;
                }
            }
        }
    }

    // --- warp reduce, stash per-half sums in SMEM ---
    #pragma unroll
    for (int j = 0; j < GL; j++) {
        #pragma unroll
        for (int o = 16; o > 0; o >>= 1)
            acc[j] += __shfl_xor_sync(0xffffffffu, acc[j], o);
    }
    if (lane == 0) {
        #pragma unroll
        for (int j = 0; j < GL; j++) sacc[grp][half][j] = acc[j];
    }
    __syncthreads();

    // --- epilogue: warp 0 lanes 0..15 each finish one lag ---
    if (warp == 0) {
        double sm = 0.0, s1 = 0.0, s2 = 0.0;
        if (lane < 16) {
            const int lg   = lane >> 3;
            const int jj   = lane & 7;
            const int lag  = 1 + GL * (part * 2 + lg) + jj;
            int nj = len - lag;
            if (nj < 0) nj = 0;
            if (nj > PP) nj = PP;
            const float tot = sacc[lg][0][jj] + sacc[lg][1][jj];
            const float msd = (nj > 0) ? tot / (float)nj : 0.f;
            const float alpha = alpha_pred[b];
            const float r = logf(msd + 1e-8f) - alpha * logf((float)lag);
            if (len > lag) {
                sm = 1.0; s1 = (double)r; s2 = (double)r * (double)r;
            }
        }
        #pragma unroll
        for (int o = 16; o > 0; o >>= 1) {
            sm += __shfl_xor_sync(0xffffffffu, sm, o);
            s1 += __shfl_xor_sync(0xffffffffu, s1, o);
            s2 += __shfl_xor_sync(0xffffffffu, s2, o);
        }
        if (lane == 0) {
            g_part[blk][0] = sm; g_part[blk][1] = s1; g_part[blk][2] = s2;
        }
    }
    __syncthreads();

    if (threadIdx.x == 0) {
        __threadfence();
        unsigned int old = atomicAdd(&g_count, 1u);
        s_last = (old == NBLK - 1) ? 1u : 0u;
    }
    __syncthreads();

    if (s_last) {
        __threadfence();
        const int t = threadIdx.x;
        if (t < NB) {
            double Sm = 0, S1 = 0, S2 = 0;
            #pragma unroll
            for (int i2 = 0; i2 < CPB; i2++) {
                Sm += g_part[CPB * t + i2][0];
                S1 += g_part[CPB * t + i2][1];
                S2 += g_part[CPB * t + i2][2];
            }
            double denom = (Sm > 1.0) ? Sm : 1.0;
            double I = S1 / denom;
            double pt = (S2 - 2.0 * I * S1 + I * I * Sm) / denom;
            spt[t] = (float)pt;
        }
        __syncthreads();
        if (threadIdx.x < 32) {
            float v = spt[threadIdx.x] + spt[threadIdx.x + 32];
            #pragma unroll
            for (int o = 16; o > 0; o >>= 1)
                v += __shfl_xor_sync(0xffffffffu, v, o);
            if (threadIdx.x == 0) {
                g_count = 0;                 // reset for next graph replay
                __threadfence();
                out[0] = v / (float)NB;
            }
        }
    }
}

// ---------------------------------------------------------------------------
// Inputs: [0] alpha_pred f32[64], [1] trajectory f32[64,1024,2],
// [2] lengths int64/int32[64]. Output: 1 float.
// ---------------------------------------------------------------------------
extern "C" void kernel_launch(void* const* d_in, const int* in_sizes, int n_in,
                              void* d_out, int out_size)
{
    const float* alpha = (const float*)d_in[0];
    const float* traj  = (const float*)d_in[1];
    const void*  lens  = d_in[2];
    float* out = (float*)d_out;

    fused_kernel<<<NBLK, NTHR>>>(traj, lens, alpha, out);
}

// round 14
// speedup vs baseline: 1.6923x; 1.1758x over previous
#include <cuda_runtime.h>
#include <math.h>

#define NB     64
#define TT     1024
#define ML     256
#define PP     (TT - 1)
#define NTHR   128          // 4 warps: 2 lag-groups x 2 position-halves
#define CPB    16           // CTAs per batch
#define NBLK   (NB * CPB)   // 1024 CTAs
#define GL     8            // lags per group

// Two-level reduction state (all zero-initialized; counters self-reset).
__device__ double g_part[NBLK][3];     // per-CTA [Sm, S1, S2]
__device__ float  g_spt[NB];           // per-batch per_traj
__device__ unsigned int g_bcount[NB];  // per-batch arrival counters
__device__ unsigned int g_count;       // global arrival counter

// lengths may arrive as int64 or int32 (JAX x64 flag dependent).
__device__ __forceinline__ int get_len(const void* Lp, int b) {
    const long long* L64 = (const long long*)Lp;
    long long v0 = L64[0];
    if (v0 >= 1 && v0 <= (long long)TT) return (int)L64[b];
    return ((const int*)Lp)[b];
}

// ---------------------------------------------------------------------------
// Main loop identical to R13 (14.27us). Changed: the cross-CTA reduction is
// two-level (per-batch counter -> global counter), tail runs entirely in
// warp 0 with lane-parallel partial reads, atomic contention split across
// 65 addresses instead of one.
// ---------------------------------------------------------------------------
__global__ void __launch_bounds__(NTHR, 7)
fused_kernel(const float* __restrict__ traj,
             const void*  __restrict__ lengths,
             const float* __restrict__ alpha_pred,
             float* __restrict__ out)
{
    __shared__ float4 sh4[TT / 2];     // positions 2k,2k+1 per float4
    __shared__ float  sacc[2][2][GL];  // [group-in-CTA][half][lag]

    const int blk  = blockIdx.x;
    const int b    = blk >> 4;        // batch
    const int part = blk & 15;        // lag slice (2 groups per CTA)

    // issue scalar loads early (independent of the bulk copy)
    const int   len   = get_len(lengths, b);
    const float alpha = alpha_pred[b];

    const float2* sh = (const float2*)sh4;

    const float4* rowq = (const float4*)(traj + (size_t)b * TT * 2);
    #pragma unroll
    for (int i = threadIdx.x; i < TT / 2; i += NTHR) sh4[i] = rowq[i];
    __syncthreads();

    const int warp = threadIdx.x >> 5;
    const int lane = threadIdx.x & 31;

    const int grp  = warp >> 1;                  // 0 or 1 within CTA
    const int half = warp & 1;                   // position half
    const int g    = part * 2 + grp;             // global group id [0,32)
    const int l0   = 1 + GL * g;                 // first lag (odd)

    int nmin = len - (l0 + GL - 1);
    if (nmin < 0) nmin = 0;
    if (nmin > PP) nmin = PP;
    int nmax = len - l0;
    if (nmax < 0) nmax = 0;
    if (nmax > PP) nmax = PP;

    float acc[GL];
    #pragma unroll
    for (int j = 0; j < GL; j++) acc[j] = 0.f;

    const int imax = nmin >> 6;
    int i = half;

    // --- main region, unrolled x2 (blocks i and i+2; half stride is 2) ---
    for (; i + 2 < imax; i += 4) {
        const int pA = (i << 6) + (lane << 1);
        const int pB = pA + 128;
        const int kA = (pA + l0 - 1) >> 1;       // even window start
        const int kB = kA + 64;

        float4 aqA = sh4[pA >> 1];
        float4 a0 = sh4[kA],     a1 = sh4[kA + 1], a2 = sh4[kA + 2];
        float4 a3 = sh4[kA + 3], a4 = sh4[kA + 4];
        float4 aqB = sh4[pB >> 1];
        float4 b0 = sh4[kB],     b1 = sh4[kB + 1], b2 = sh4[kB + 2];
        float4 b3 = sh4[kB + 3], b4 = sh4[kB + 4];

        float ax[10], ay[10], bx[10], by[10];    // window pos l0-1 .. l0+8
        ax[0]=a0.x; ay[0]=a0.y; ax[1]=a0.z; ay[1]=a0.w;
        ax[2]=a1.x; ay[2]=a1.y; ax[3]=a1.z; ay[3]=a1.w;
        ax[4]=a2.x; ay[4]=a2.y; ax[5]=a2.z; ay[5]=a2.w;
        ax[6]=a3.x; ay[6]=a3.y; ax[7]=a3.z; ay[7]=a3.w;
        ax[8]=a4.x; ay[8]=a4.y; ax[9]=a4.z; ay[9]=a4.w;
        bx[0]=b0.x; by[0]=b0.y; bx[1]=b0.z; by[1]=b0.w;
        bx[2]=b1.x; by[2]=b1.y; bx[3]=b1.z; by[3]=b1.w;
        bx[4]=b2.x; by[4]=b2.y; bx[5]=b2.z; by[5]=b2.w;
        bx[6]=b3.x; by[6]=b3.y; bx[7]=b3.z; by[7]=b3.w;
        bx[8]=b4.x; by[8]=b4.y; bx[9]=b4.z; by[9]=b4.w;

        #pragma unroll
        for (int j = 0; j < GL; j++) {
            float dx0 = ax[j+1] - aqA.x, dy0 = ay[j+1] - aqA.y;
            float dx1 = ax[j+2] - aqA.z, dy1 = ay[j+2] - aqA.w;
            float ex0 = bx[j+1] - aqB.x, ey0 = by[j+1] - aqB.y;
            float ex1 = bx[j+2] - aqB.z, ey1 = by[j+2] - aqB.w;
            acc[j] += dx0 * dx0 + dy0 * dy0;
            acc[j] += dx1 * dx1 + dy1 * dy1;
            acc[j] += ex0 * ex0 + ey0 * ey0;
            acc[j] += ex1 * ex1 + ey1 * ey1;
        }
    }

    // --- leftover single block for this half ---
    if (i < imax) {
        const int p  = (i << 6) + (lane << 1);
        const int k0 = (p + l0 - 1) >> 1;
        float4 aq = sh4[p >> 1];
        float4 q0 = sh4[k0],     q1 = sh4[k0 + 1], q2 = sh4[k0 + 2];
        float4 q3 = sh4[k0 + 3], q4 = sh4[k0 + 4];

        float vx[10], vy[10];
        vx[0]=q0.x; vy[0]=q0.y; vx[1]=q0.z; vy[1]=q0.w;
        vx[2]=q1.x; vy[2]=q1.y; vx[3]=q1.z; vy[3]=q1.w;
        vx[4]=q2.x; vy[4]=q2.y; vx[5]=q2.z; vy[5]=q2.w;
        vx[6]=q3.x; vy[6]=q3.y; vx[7]=q3.z; vy[7]=q3.w;
        vx[8]=q4.x; vy[8]=q4.y; vx[9]=q4.z; vy[9]=q4.w;

        #pragma unroll
        for (int j = 0; j < GL; j++) {
            float dx0 = vx[j+1] - aq.x, dy0 = vy[j+1] - aq.y;
            float dx1 = vx[j+2] - aq.z, dy1 = vy[j+2] - aq.w;
            acc[j] += dx0 * dx0 + dy0 * dy0;
            acc[j] += dx1 * dx1 + dy1 * dy1;
        }
    }

    // --- masked tail (half 1 only) ---
    if (half == 1) {
        for (int p = (imax << 6) + lane; p < nmax; p += 32) {
            float2 a = sh[p];
            #pragma unroll
            for (int j = 0; j < GL; j++) {
                int nj = len - (l0 + j);
                if (nj > PP) nj = PP;
                if (p < nj) {
                    float2 e = sh[p + l0 + j];
                    float dx = e.x - a.x, dy = e.y - a.y;
                    acc[j] += dx * dx + dy * dy;
                }
            }
        }
    }

    // --- warp reduce, stash per-half sums in SMEM ---
    #pragma unroll
    for (int j = 0; j < GL; j++) {
        #pragma unroll
        for (int o = 16; o > 0; o >>= 1)
            acc[j] += __shfl_xor_sync(0xffffffffu, acc[j], o);
    }
    if (lane == 0) {
        #pragma unroll
        for (int j = 0; j < GL; j++) sacc[grp][half][j] = acc[j];
    }
    __syncthreads();

    // ======================= tail: warp 0 only =======================
    if (warp == 0) {
        // per-lag stats for this CTA's 16 lags (lanes 0..15)
        double sm = 0.0, s1 = 0.0, s2 = 0.0;
        if (lane < 16) {
            const int lg   = lane >> 3;
            const int jj   = lane & 7;
            const int lag  = 1 + GL * (part * 2 + lg) + jj;
            int nj = len - lag;
            if (nj < 0) nj = 0;
            if (nj > PP) nj = PP;
            const float tot = sacc[lg][0][jj] + sacc[lg][1][jj];
            const float msd = (nj > 0) ? tot / (float)nj : 0.f;
            const float r = logf(msd + 1e-8f) - alpha * logf((float)lag);
            if (len > lag) {
                sm = 1.0; s1 = (double)r; s2 = (double)r * (double)r;
            }
        }
        #pragma unroll
        for (int o = 16; o > 0; o >>= 1) {
            sm += __shfl_xor_sync(0xffffffffu, sm, o);
            s1 += __shfl_xor_sync(0xffffffffu, s1, o);
            s2 += __shfl_xor_sync(0xffffffffu, s2, o);
        }

        unsigned int oldb = 0u;
        if (lane == 0) {
            g_part[blk][0] = sm; g_part[blk][1] = s1; g_part[blk][2] = s2;
            __threadfence();
            oldb = atomicAdd(&g_bcount[b], 1u);
        }
        oldb = __shfl_sync(0xffffffffu, oldb, 0);

        if (oldb == CPB - 1) {
            // ---- per-batch last CTA: reduce 16 partials (lane-parallel) ----
            __threadfence();
            double Sm = 0.0, S1 = 0.0, S2 = 0.0;
            if (lane < CPB) {
                const int idx = b * CPB + lane;
                Sm = g_part[idx][0];
                S1 = g_part[idx][1];
                S2 = g_part[idx][2];
            }
            #pragma unroll
            for (int o = 16; o > 0; o >>= 1) {
                Sm += __shfl_xor_sync(0xffffffffu, Sm, o);
                S1 += __shfl_xor_sync(0xffffffffu, S1, o);
                S2 += __shfl_xor_sync(0xffffffffu, S2, o);
            }
            unsigned int oldg = 0u;
            if (lane == 0) {
                double denom = (Sm > 1.0) ? Sm : 1.0;
                double I = S1 / denom;
                double pt = (S2 - 2.0 * I * S1 + I * I * Sm) / denom;
                g_spt[b] = (float)pt;
                g_bcount[b] = 0;             // reset for next replay
                __threadfence();
                oldg = atomicAdd(&g_count, 1u);
            }
            oldg = __shfl_sync(0xffffffffu, oldg, 0);

            if (oldg == NB - 1) {
                // ---- global last: reduce 64 per-batch values ----
                __threadfence();
                float v = g_spt[lane] + g_spt[lane + 32];
                #pragma unroll
                for (int o = 16; o > 0; o >>= 1)
                    v += __shfl_xor_sync(0xffffffffu, v, o);
                if (lane == 0) {
                    g_count = 0;             // reset for next replay
                    __threadfence();
                    out[0] = v / (float)NB;
                }
            }
        }
    }
}

// ---------------------------------------------------------------------------
// Inputs: [0] alpha_pred f32[64], [1] trajectory f32[64,1024,2],
// [2] lengths int64/int32[64]. Output: 1 float.
// ---------------------------------------------------------------------------
extern "C" void kernel_launch(void* const* d_in, const int* in_sizes, int n_in,
                              void* d_out, int out_size)
{
    const float* alpha = (const float*)d_in[0];
    const float* traj  = (const float*)d_in[1];
    const void*  lens  = d_in[2];
    float* out = (float*)d_out;

    fused_kernel<<<NBLK, NTHR>>>(traj, lens, alpha, out);
}